// round 6
// baseline (speedup 1.0000x reference)
#include <cuda_runtime.h>
#include <cuda_bf16.h>

// Dataset: N_NODES = 1e6, N_EDGES = 32e6, edge_index int32 (JAX x64-off downcast).
#define MAX_NODES 1000000

__device__ float g_agg1[MAX_NODES];
__device__ float g_agg2[MAX_NODES];

// ---------------------------------------------------------------------------
// Scatter-add pass: 4 edges per thread (int4 index loads), one iter per thread.
//   RELU_W == false: agg[dst] += vals[src]
//   RELU_W == true : agg[dst] += max(vals[src]*w, 0)
// Gathers via __ldg (L1 gets ~6% hit on the 4MB table — free). atomicAdd with
// unused result compiles to REDG (no return trip).
// ---------------------------------------------------------------------------
template <bool RELU_W>
__global__ __launch_bounds__(256, 8)
void scatter_kernel(const int* __restrict__ src,
                    const int* __restrict__ dst,
                    const float* __restrict__ vals,
                    const float* __restrict__ wptr,
                    float* __restrict__ agg,
                    int n_edges) {
    const float w = RELU_W ? __ldg(wptr) : 0.0f;

    int tid = blockIdx.x * blockDim.x + threadIdx.x;
    int stride = gridDim.x * blockDim.x;

    const int4* src4 = reinterpret_cast<const int4*>(src);
    const int4* dst4 = reinterpret_cast<const int4*>(dst);

    int n_quads = n_edges >> 2;
    for (int i = tid; i < n_quads; i += stride) {
        int4 s = src4[i];
        int4 d = dst4[i];

        float v0 = __ldg(&vals[s.x]);
        float v1 = __ldg(&vals[s.y]);
        float v2 = __ldg(&vals[s.z]);
        float v3 = __ldg(&vals[s.w]);
        if (RELU_W) {
            v0 = fmaxf(v0 * w, 0.0f);
            v1 = fmaxf(v1 * w, 0.0f);
            v2 = fmaxf(v2 * w, 0.0f);
            v3 = fmaxf(v3 * w, 0.0f);
        }
        atomicAdd(&agg[d.x], v0);
        atomicAdd(&agg[d.y], v1);
        atomicAdd(&agg[d.z], v2);
        atomicAdd(&agg[d.w], v3);
    }

    // tail (only if n_edges % 4 != 0)
    for (int e = (n_quads << 2) + tid; e < n_edges; e += stride) {
        int s = src[e];
        int d = dst[e];
        float t = __ldg(&vals[s]);
        if (RELU_W) t = fmaxf(t * w, 0.0f);
        atomicAdd(&agg[d], t);
    }
}

// ---------------------------------------------------------------------------
// epilogue: out = sigmoid(relu(agg2 * w2)), float4-vectorized
// ---------------------------------------------------------------------------
__global__ __launch_bounds__(256)
void epilogue_kernel(const float* __restrict__ w2ptr,
                     float* __restrict__ out, int n) {
    const float w2 = __ldg(w2ptr);
    int i = blockIdx.x * blockDim.x + threadIdx.x;
    int stride = gridDim.x * blockDim.x;

    const float4* a4 = reinterpret_cast<const float4*>(g_agg2);
    float4* o4 = reinterpret_cast<float4*>(out);
    int n4 = n >> 2;
    for (int j = i; j < n4; j += stride) {
        float4 a = a4[j];
        float4 r;
        r.x = 1.0f / (1.0f + __expf(-fmaxf(a.x * w2, 0.0f)));
        r.y = 1.0f / (1.0f + __expf(-fmaxf(a.y * w2, 0.0f)));
        r.z = 1.0f / (1.0f + __expf(-fmaxf(a.z * w2, 0.0f)));
        r.w = 1.0f / (1.0f + __expf(-fmaxf(a.w * w2, 0.0f)));
        o4[j] = r;
    }
    for (int j = (n4 << 2) + i; j < n; j += stride) {
        float h = fmaxf(g_agg2[j] * w2, 0.0f);
        out[j] = 1.0f / (1.0f + __expf(-h));
    }
}

// ---------------------------------------------------------------------------
extern "C" void kernel_launch(void* const* d_in, const int* in_sizes, int n_in,
                              void* d_out, int out_size) {
    const float* x  = (const float*)d_in[0];
    const int* ei   = (const int*)d_in[1];
    const float* w1 = (const float*)d_in[2];
    const float* w2 = (const float*)d_in[3];
    float* out = (float*)d_out;

    const int n_nodes = in_sizes[0];
    const int n_edges = in_sizes[1] / 2;
    const int* src = ei;
    const int* dst = ei + n_edges;

    float* agg1; float* agg2;
    cudaGetSymbolAddress((void**)&agg1, g_agg1);
    cudaGetSymbolAddress((void**)&agg2, g_agg2);

    // 1) zero scratch via memset nodes (graph-capturable, ~full DRAM bw)
    cudaMemsetAsync(agg1, 0, (size_t)n_nodes * sizeof(float));
    cudaMemsetAsync(agg2, 0, (size_t)n_nodes * sizeof(float));

    // scatter grid: 4 edges per thread, one iteration per thread
    int threads = 256;
    long long want = ((long long)n_edges / 4 + threads - 1) / threads;
    int blocks = (int)(want > 1048576LL ? 1048576LL : want);
    if (blocks < 1) blocks = 1;

    // 2) pass 1: agg1[dst] += x[src]
    scatter_kernel<false><<<blocks, threads>>>(src, dst, x, w1, agg1, n_edges);

    // 3) pass 2: agg2[dst] += relu(agg1[src] * w1)
    scatter_kernel<true><<<blocks, threads>>>(src, dst, agg1, w1, agg2, n_edges);

    // 4) epilogue (vectorized)
    {
        int eblocks = ((n_nodes >> 2) + threads - 1) / threads;
        if (eblocks > 2048) eblocks = 2048;
        if (eblocks < 1) eblocks = 1;
        epilogue_kernel<<<eblocks, threads>>>(w2, out, n_nodes);
    }
}

// round 7
// speedup vs baseline: 1.0211x; 1.0211x over previous
#include <cuda_runtime.h>
#include <cuda_bf16.h>

// Dataset: N_NODES = 1e6, N_EDGES = 32e6, edge_index int32 (JAX x64-off downcast).
#define MAX_NODES 1000000

__device__ float g_agg1[MAX_NODES];
__device__ float g_agg2[MAX_NODES];

// ---------------------------------------------------------------------------
// Scatter-add pass: 4 edges/thread, int4 index loads with streaming hint
// (__ldcs: the 256MB index stream is read-once — keep x/agg L2-resident).
//   RELU_W == false: agg[dst] += vals[src]
//   RELU_W == true : agg[dst] += max(vals[src]*w, 0)
// Gathers via __ldg (the ~6% L1 hits on the 4MB table are free LTS savings).
// atomicAdd with unused result compiles to REDG (no return trip).
// ---------------------------------------------------------------------------
template <bool RELU_W>
__global__ __launch_bounds__(256)
void scatter_kernel(const int4* __restrict__ src4,
                    const int4* __restrict__ dst4,
                    const float* __restrict__ vals,
                    const float* __restrict__ wptr,
                    float* __restrict__ agg,
                    int n_quads, int n_edges) {
    const float w = RELU_W ? __ldg(wptr) : 0.0f;

    int tid = blockIdx.x * blockDim.x + threadIdx.x;
    int stride = gridDim.x * blockDim.x;

    for (int i = tid; i < n_quads; i += stride) {
        int4 s = __ldcs(&src4[i]);
        int4 d = __ldcs(&dst4[i]);

        float v0 = __ldg(&vals[s.x]);
        float v1 = __ldg(&vals[s.y]);
        float v2 = __ldg(&vals[s.z]);
        float v3 = __ldg(&vals[s.w]);
        if (RELU_W) {
            v0 = fmaxf(v0 * w, 0.0f);
            v1 = fmaxf(v1 * w, 0.0f);
            v2 = fmaxf(v2 * w, 0.0f);
            v3 = fmaxf(v3 * w, 0.0f);
        }
        atomicAdd(&agg[d.x], v0);
        atomicAdd(&agg[d.y], v1);
        atomicAdd(&agg[d.z], v2);
        atomicAdd(&agg[d.w], v3);
    }

    // tail (only if n_edges % 4 != 0; dataset: never)
    const int* src = (const int*)src4;
    const int* dst = (const int*)dst4;
    for (int e = (n_quads << 2) + tid; e < n_edges; e += stride) {
        float t = __ldg(&vals[src[e]]);
        if (RELU_W) t = fmaxf(t * w, 0.0f);
        atomicAdd(&agg[dst[e]], t);
    }
}

// ---------------------------------------------------------------------------
// epilogue: out = sigmoid(relu(agg2 * w2)), float4-vectorized
// ---------------------------------------------------------------------------
__global__ __launch_bounds__(256)
void epilogue_kernel(const float* __restrict__ w2ptr,
                     float* __restrict__ out, int n) {
    const float w2 = __ldg(w2ptr);
    int i = blockIdx.x * blockDim.x + threadIdx.x;
    int stride = gridDim.x * blockDim.x;

    const float4* a4 = reinterpret_cast<const float4*>(g_agg2);
    float4* o4 = reinterpret_cast<float4*>(out);
    int n4 = n >> 2;
    for (int j = i; j < n4; j += stride) {
        float4 a = a4[j];
        float4 r;
        r.x = 1.0f / (1.0f + __expf(-fmaxf(a.x * w2, 0.0f)));
        r.y = 1.0f / (1.0f + __expf(-fmaxf(a.y * w2, 0.0f)));
        r.z = 1.0f / (1.0f + __expf(-fmaxf(a.z * w2, 0.0f)));
        r.w = 1.0f / (1.0f + __expf(-fmaxf(a.w * w2, 0.0f)));
        o4[j] = r;
    }
    for (int j = (n4 << 2) + i; j < n; j += stride) {
        float h = fmaxf(g_agg2[j] * w2, 0.0f);
        out[j] = 1.0f / (1.0f + __expf(-h));
    }
}

// ---------------------------------------------------------------------------
extern "C" void kernel_launch(void* const* d_in, const int* in_sizes, int n_in,
                              void* d_out, int out_size) {
    const float* x  = (const float*)d_in[0];
    const int* ei   = (const int*)d_in[1];
    const float* w1 = (const float*)d_in[2];
    const float* w2 = (const float*)d_in[3];
    float* out = (float*)d_out;

    const int n_nodes = in_sizes[0];
    const int n_edges = in_sizes[1] / 2;
    const int4* src4 = (const int4*)ei;
    const int4* dst4 = (const int4*)(ei + n_edges);

    float* agg1; float* agg2;
    cudaGetSymbolAddress((void**)&agg1, g_agg1);
    cudaGetSymbolAddress((void**)&agg2, g_agg2);

    // 1) zero scratch via memset nodes (graph-capturable)
    cudaMemsetAsync(agg1, 0, (size_t)n_nodes * sizeof(float));
    cudaMemsetAsync(agg2, 0, (size_t)n_nodes * sizeof(float));

    // scatter grid: 4 edges/thread, exactly one iteration per thread
    const int threads = 256;
    int n_quads = n_edges >> 2;
    long long want = ((long long)n_quads + threads - 1) / threads;
    int blocks = (int)(want > 1048576LL ? 1048576LL : want);
    if (blocks < 1) blocks = 1;

    // 2) pass 1: agg1[dst] += x[src]
    scatter_kernel<false><<<blocks, threads>>>(src4, dst4, x, w1, agg1,
                                               n_quads, n_edges);

    // 3) pass 2: agg2[dst] += relu(agg1[src] * w1)
    scatter_kernel<true><<<blocks, threads>>>(src4, dst4, agg1, w1, agg2,
                                              n_quads, n_edges);

    // 4) epilogue (vectorized)
    {
        int eblocks = ((n_nodes >> 2) + threads - 1) / threads;
        if (eblocks > 2048) eblocks = 2048;
        if (eblocks < 1) eblocks = 1;
        epilogue_kernel<<<eblocks, threads>>>(w2, out, n_nodes);
    }
}

// round 8
// speedup vs baseline: 1.0343x; 1.0129x over previous
#include <cuda_runtime.h>
#include <cuda_bf16.h>

// Dataset: N_NODES = 1e6, N_EDGES = 32e6, edge_index int32 (JAX x64-off downcast).
//
// Converged design (R7 post-mortem): the scatter passes run at 94.5% of the
// path-independent LTS cap (~6300 B/cyc). Per pass: 0.25GB coalesced index
// stream (the only DRAM traffic) + ~1GB random gather sectors + ~1GB RED
// sectors, all through L2 (x/agg are L2-resident, 4MB each). Every reordering
// scheme measured (src-bucket, dst counting-sort, smem accumulation) costs
// more LTS/smem-atomic traffic to build than it saves for a 2-layer model.
#define MAX_NODES 1000000

// Single scratch region so one memset node covers both buffers.
__device__ float g_agg[2 * MAX_NODES];

// ---------------------------------------------------------------------------
// Scatter-add pass: 4 edges/thread, one iteration per thread.
//   RELU_W == false: agg[dst] += vals[src]
//   RELU_W == true : agg[dst] += max(vals[src]*w, 0)
// Index stream via __ldcs (read-once, keep x/agg resident); gathers via __ldg
// (~6% free L1 hits); atomicAdd w/ unused result -> REDG (no return trip).
// ---------------------------------------------------------------------------
template <bool RELU_W>
__global__ __launch_bounds__(256)
void scatter_kernel(const int4* __restrict__ src4,
                    const int4* __restrict__ dst4,
                    const float* __restrict__ vals,
                    const float* __restrict__ wptr,
                    float* __restrict__ agg,
                    int n_quads, int n_edges) {
    const float w = RELU_W ? __ldg(wptr) : 0.0f;

    int tid = blockIdx.x * blockDim.x + threadIdx.x;
    int stride = gridDim.x * blockDim.x;

    for (int i = tid; i < n_quads; i += stride) {
        int4 s = __ldcs(&src4[i]);
        int4 d = __ldcs(&dst4[i]);

        float v0 = __ldg(&vals[s.x]);
        float v1 = __ldg(&vals[s.y]);
        float v2 = __ldg(&vals[s.z]);
        float v3 = __ldg(&vals[s.w]);
        if (RELU_W) {
            v0 = fmaxf(v0 * w, 0.0f);
            v1 = fmaxf(v1 * w, 0.0f);
            v2 = fmaxf(v2 * w, 0.0f);
            v3 = fmaxf(v3 * w, 0.0f);
        }
        atomicAdd(&agg[d.x], v0);
        atomicAdd(&agg[d.y], v1);
        atomicAdd(&agg[d.z], v2);
        atomicAdd(&agg[d.w], v3);
    }

    // tail (only if n_edges % 4 != 0; dataset: never)
    const int* src = (const int*)src4;
    const int* dst = (const int*)dst4;
    for (int e = (n_quads << 2) + tid; e < n_edges; e += stride) {
        float t = __ldg(&vals[src[e]]);
        if (RELU_W) t = fmaxf(t * w, 0.0f);
        atomicAdd(&agg[dst[e]], t);
    }
}

// ---------------------------------------------------------------------------
// epilogue: out = sigmoid(relu(agg2 * w2)), float4-vectorized
// ---------------------------------------------------------------------------
__global__ __launch_bounds__(256)
void epilogue_kernel(const float* __restrict__ w2ptr,
                     const float* __restrict__ agg2,
                     float* __restrict__ out, int n) {
    const float w2 = __ldg(w2ptr);
    int i = blockIdx.x * blockDim.x + threadIdx.x;
    int stride = gridDim.x * blockDim.x;

    const float4* a4 = reinterpret_cast<const float4*>(agg2);
    float4* o4 = reinterpret_cast<float4*>(out);
    int n4 = n >> 2;
    for (int j = i; j < n4; j += stride) {
        float4 a = a4[j];
        float4 r;
        r.x = 1.0f / (1.0f + __expf(-fmaxf(a.x * w2, 0.0f)));
        r.y = 1.0f / (1.0f + __expf(-fmaxf(a.y * w2, 0.0f)));
        r.z = 1.0f / (1.0f + __expf(-fmaxf(a.z * w2, 0.0f)));
        r.w = 1.0f / (1.0f + __expf(-fmaxf(a.w * w2, 0.0f)));
        o4[j] = r;
    }
    for (int j = (n4 << 2) + i; j < n; j += stride) {
        float h = fmaxf(agg2[j] * w2, 0.0f);
        out[j] = 1.0f / (1.0f + __expf(-h));
    }
}

// ---------------------------------------------------------------------------
extern "C" void kernel_launch(void* const* d_in, const int* in_sizes, int n_in,
                              void* d_out, int out_size) {
    const float* x  = (const float*)d_in[0];
    const int* ei   = (const int*)d_in[1];
    const float* w1 = (const float*)d_in[2];
    const float* w2 = (const float*)d_in[3];
    float* out = (float*)d_out;

    const int n_nodes = in_sizes[0];
    const int n_edges = in_sizes[1] / 2;
    const int4* src4 = (const int4*)ei;
    const int4* dst4 = (const int4*)(ei + n_edges);

    float* aggbase;
    cudaGetSymbolAddress((void**)&aggbase, g_agg);
    float* agg1 = aggbase;
    float* agg2 = aggbase + MAX_NODES;

    // 1) zero both scratch buffers with ONE memset node
    cudaMemsetAsync(aggbase, 0, (size_t)2 * MAX_NODES * sizeof(float));

    // scatter grid: 4 edges/thread, exactly one iteration per thread
    const int threads = 256;
    int n_quads = n_edges >> 2;
    long long want = ((long long)n_quads + threads - 1) / threads;
    int blocks = (int)(want > 1048576LL ? 1048576LL : want);
    if (blocks < 1) blocks = 1;

    // 2) pass 1: agg1[dst] += x[src]
    scatter_kernel<false><<<blocks, threads>>>(src4, dst4, x, w1, agg1,
                                               n_quads, n_edges);

    // 3) pass 2: agg2[dst] += relu(agg1[src] * w1)
    scatter_kernel<true><<<blocks, threads>>>(src4, dst4, agg1, w1, agg2,
                                              n_quads, n_edges);

    // 4) epilogue (vectorized)
    {
        int eblocks = ((n_nodes >> 2) + threads - 1) / threads;
        if (eblocks > 2048) eblocks = 2048;
        if (eblocks < 1) eblocks = 1;
        epilogue_kernel<<<eblocks, threads>>>(w2, agg2, out, n_nodes);
    }
}